// round 12
// baseline (speedup 1.0000x reference)
#include <cuda_runtime.h>
#include <cuda_bf16.h>
#include <cstdint>
#include <math.h>

#define NA 1000
#define KP 100000
#define BD 256
#define KPAD 1024
#define RICH_ITERS 11
#define POW_ITERS 6
#define NCTA_SOLVE 16

// Tile: CTA 128x128, BK=32, 8 warps (4m x 2n), warp tile 32x64.
// Smem tile: 128 rows x 40 halves (32 data + 8 pad) = 10240 B; 4 tiles/stage.
#define TILE_B  10240
#define STAGE_B (4 * TILE_B)   // 40960

// ---------------- device scratch ----------------
__device__ __align__(16) __nv_bfloat16 g_pubH[(size_t)NA * KP];
__device__ __align__(16) __nv_bfloat16 g_pubL[(size_t)NA * KP];
__device__ __align__(16) __nv_bfloat16 g_pubTH[(size_t)KP * KPAD];
__device__ __align__(16) __nv_bfloat16 g_pubTL[(size_t)KP * KPAD];
__device__ __align__(16) __nv_bfloat16 g_privH[(size_t)BD * KP];
__device__ __align__(16) __nv_bfloat16 g_privL[(size_t)BD * KP];
__device__ __align__(16) __nv_bfloat16 g_SH[NA * KPAD];
__device__ __align__(16) __nv_bfloat16 g_SL[NA * KPAD];
__device__ __align__(16) __nv_bfloat16 g_XH0[BD * KPAD];
__device__ __align__(16) __nv_bfloat16 g_XL0[BD * KPAD];
__device__ __align__(16) __nv_bfloat16 g_XH1[BD * KPAD];
__device__ __align__(16) __nv_bfloat16 g_XL1[BD * KPAD];
__device__ float g_S [NA * NA];
__device__ float g_Sp[8][NA * NA];
__device__ float g_Cm[BD * NA];
__device__ float g_Cp[16][BD * NA];
__device__ float g_X [BD * NA];
__device__ float g_v[NA], g_y[NA];
__device__ float g_lam, g_alpha;
__device__ float g_scale[BD];
__device__ unsigned int g_bar;

// ---------------- PTX helpers ----------------
__device__ __forceinline__ uint32_t smem_u32(const void* p) {
    uint32_t a;
    asm("{ .reg .u64 t; cvta.to.shared.u64 t, %1; cvt.u32.u64 %0, t; }" : "=r"(a) : "l"(p));
    return a;
}
__device__ __forceinline__ void ldsm4(uint32_t addr, uint32_t& r0, uint32_t& r1,
                                      uint32_t& r2, uint32_t& r3) {
    asm volatile("ldmatrix.sync.aligned.m8n8.x4.shared.b16 {%0,%1,%2,%3}, [%4];"
                 : "=r"(r0), "=r"(r1), "=r"(r2), "=r"(r3) : "r"(addr));
}
__device__ __forceinline__ void mma16816(float* c, const uint32_t* a, const uint32_t* b) {
    asm volatile(
        "mma.sync.aligned.m16n8k16.row.col.f32.bf16.bf16.f32 "
        "{%0,%1,%2,%3}, {%4,%5,%6,%7}, {%8,%9}, {%0,%1,%2,%3};"
        : "+f"(c[0]), "+f"(c[1]), "+f"(c[2]), "+f"(c[3])
        : "r"(a[0]), "r"(a[1]), "r"(a[2]), "r"(a[3]), "r"(b[0]), "r"(b[1]));
}
template <bool CG>
__device__ __forceinline__ void cpa16(uint32_t dst, const void* src, int srcsz) {
    if (CG)
        asm volatile("cp.async.cg.shared.global [%0], [%1], 16, %2;"
                     :: "r"(dst), "l"(src), "r"(srcsz));
    else
        asm volatile("cp.async.ca.shared.global [%0], [%1], 16, %2;"
                     :: "r"(dst), "l"(src), "r"(srcsz));
}
#define CP_COMMIT() asm volatile("cp.async.commit_group;" ::: "memory")

// async tile load: bf16 K-major rows; 512 uint4 per tile, 2 per thread.
// rows beyond `rows` are ZERO-filled (src-size 0 => zero fill).
template <bool CG>
__device__ __forceinline__ void ldt_async(const __nv_bfloat16* __restrict__ src, long long ld,
                                          int row0, int rows, int kb, uint32_t dst) {
    #pragma unroll
    for (int i = 0; i < 2; i++) {
        int e = threadIdx.x + i * 256;
        int r = e >> 2, q = e & 3;
        int gr = row0 + r;
        int sz = (gr < rows) ? 16 : 0;
        int rr = (gr < rows) ? gr : (rows - 1);
        cpa16<CG>(dst + r * 80 + q * 16, &src[(long long)rr * ld + kb + q * 8], sz);
    }
}

// ---------------------------------------------------------------------------
// Shared pipelined mainloop: acc += A[m0.., kb0..] * B[n0.., kb0..]^T
// bf16 hi/lo 2-term split, 3 MMA passes, cp.async 2-stage double buffer.
// ---------------------------------------------------------------------------
template <bool CG>
__device__ __forceinline__ void gemm_mainloop(
    const __nv_bfloat16* __restrict__ Ah, const __nv_bfloat16* __restrict__ Al,
    long long lda, int Mrows, int m0,
    const __nv_bfloat16* __restrict__ Bh, const __nv_bfloat16* __restrict__ Bl,
    long long ldb, int Nrows, int n0,
    int kb0, int nch, uint32_t sbase, float acc[2][8][4])
{
    const int lane = threadIdx.x & 31, wid = threadIdx.x >> 5;
    const int wm = wid >> 1, wn = wid & 1;
    const int aRow = wm * 32 + (lane & 15);
    const int aKof = (lane >> 4) * 8;
    const int bRowBase = wn * 64 + (lane & 7) + ((lane >> 4) << 3);
    const int bKof = ((lane >> 3) & 1) << 3;

    // prologue: stage 0
    {
        const int kb = kb0;
        ldt_async<CG>(Ah, lda, m0, Mrows, kb, sbase);
        ldt_async<CG>(Al, lda, m0, Mrows, kb, sbase + TILE_B);
        ldt_async<CG>(Bh, ldb, n0, Nrows, kb, sbase + 2 * TILE_B);
        ldt_async<CG>(Bl, ldb, n0, Nrows, kb, sbase + 3 * TILE_B);
        CP_COMMIT();
    }
    for (int c = 0; c < nch; c++) {
        if (c + 1 < nch) {
            const int kb = kb0 + (c + 1) * 32;
            const uint32_t st = sbase + ((c + 1) & 1) * STAGE_B;
            ldt_async<CG>(Ah, lda, m0, Mrows, kb, st);
            ldt_async<CG>(Al, lda, m0, Mrows, kb, st + TILE_B);
            ldt_async<CG>(Bh, ldb, n0, Nrows, kb, st + 2 * TILE_B);
            ldt_async<CG>(Bl, ldb, n0, Nrows, kb, st + 3 * TILE_B);
            CP_COMMIT();
            asm volatile("cp.async.wait_group 1;" ::: "memory");
        } else {
            asm volatile("cp.async.wait_group 0;" ::: "memory");
        }
        __syncthreads();

        const uint32_t uS = sbase + (c & 1) * STAGE_B;
        const uint32_t uAh = uS, uAl = uS + TILE_B;
        const uint32_t uBh = uS + 2 * TILE_B, uBl = uS + 3 * TILE_B;
        #pragma unroll
        for (int ks = 0; ks < 2; ks++) {
            uint32_t ah[2][4], al[2][4];
            #pragma unroll
            for (int mf = 0; mf < 2; mf++) {
                uint32_t ao = (uint32_t)((aRow + mf * 16) * 80 + (ks * 16 + aKof) * 2);
                ldsm4(uAh + ao, ah[mf][0], ah[mf][1], ah[mf][2], ah[mf][3]);
                ldsm4(uAl + ao, al[mf][0], al[mf][1], al[mf][2], al[mf][3]);
            }
            #pragma unroll
            for (int nf2 = 0; nf2 < 4; nf2++) {
                uint32_t bh[4], bl[4];
                uint32_t bo = (uint32_t)((bRowBase + nf2 * 16) * 80 + (ks * 16 + bKof) * 2);
                ldsm4(uBh + bo, bh[0], bh[1], bh[2], bh[3]);
                ldsm4(uBl + bo, bl[0], bl[1], bl[2], bl[3]);
                #pragma unroll
                for (int h = 0; h < 2; h++) {
                    const int nf = nf2 * 2 + h;
                    uint32_t* bhp = &bh[h * 2];
                    uint32_t* blp = &bl[h * 2];
                    #pragma unroll
                    for (int mf = 0; mf < 2; mf++) {
                        mma16816(acc[mf][nf], ah[mf], bhp);
                        mma16816(acc[mf][nf], ah[mf], blp);
                        mma16816(acc[mf][nf], al[mf], bhp);
                    }
                }
            }
        }
        __syncthreads();
    }
}

// ---------------------------------------------------------------------------
// GEMM kernel. mode 0: partial store to outp + z*sliceStride.
//              mode 1: out = aux2[m]*t + clamp(aux[m,n]-t, +-1e-3)
// ---------------------------------------------------------------------------
__global__ void __launch_bounds__(256, 2)
gemm_tc(const __nv_bfloat16* __restrict__ Ah, const __nv_bfloat16* __restrict__ Al,
        long long lda, int Mrows,
        const __nv_bfloat16* __restrict__ Bh, const __nv_bfloat16* __restrict__ Bl,
        long long ldb, int Nrows,
        int K, int chunksPer,
        float* __restrict__ outp, long long sliceStride, long long ldc,
        int mode, const float* __restrict__ aux, long long ldaux,
        const float* __restrict__ aux2, int tri)
{
    if (tri && blockIdx.x > blockIdx.y) return;
    const int m0 = blockIdx.y * 128, n0 = blockIdx.x * 128, z = blockIdx.z;
    const int kb0 = z * chunksPer * 32;
    const int kend = min(K, kb0 + chunksPer * 32);
    if (kb0 >= kend) return;
    const int nch = (kend - kb0) >> 5;

    extern __shared__ __align__(16) char smem[];
    const uint32_t sbase = smem_u32(smem);
    const int lane = threadIdx.x & 31, wid = threadIdx.x >> 5;
    const int wm = wid >> 1, wn = wid & 1;

    float acc[2][8][4];
    #pragma unroll
    for (int i = 0; i < 2; i++)
        #pragma unroll
        for (int j = 0; j < 8; j++)
            #pragma unroll
            for (int q = 0; q < 4; q++) acc[i][j][q] = 0.f;

    gemm_mainloop<false>(Ah, Al, lda, Mrows, m0, Bh, Bl, ldb, Nrows, n0,
                         kb0, nch, sbase, acc);

    float* po = outp + (size_t)z * (size_t)sliceStride;
    #pragma unroll
    for (int mf = 0; mf < 2; mf++) {
        #pragma unroll
        for (int hh = 0; hh < 2; hh++) {
            const int m = m0 + wm * 32 + mf * 16 + (lane >> 2) + hh * 8;
            if (m >= Mrows) continue;
            const float sc = (mode == 1) ? aux2[m] : 0.f;
            #pragma unroll
            for (int nf = 0; nf < 8; nf++) {
                const int nb = n0 + wn * 64 + nf * 8 + (lane & 3) * 2;
                #pragma unroll
                for (int j = 0; j < 2; j++) {
                    const int n = nb + j;
                    if (n >= Nrows) continue;
                    const float t = acc[mf][nf][hh * 2 + j];
                    size_t ix = (size_t)m * ldc + n;
                    if (mode == 1) {
                        float rr = aux[(size_t)m * ldaux + n] - t;
                        rr = fminf(fmaxf(rr, -1e-3f), 1e-3f);
                        po[ix] = sc * t + rr;
                    } else {
                        po[ix] = t;
                    }
                }
            }
        }
    }
}

// ---------------------------------------------------------------------------
// Persistent solve kernel: initX + RICH_ITERS Richardson + clip scale.
// 16 CTAs, monotonic grid barrier. Hardened: release-arrive, acquire-poll
// with nanosleep backoff (g_bar reset by zerobar_k earlier in the graph).
// ---------------------------------------------------------------------------
__device__ __forceinline__ void gridbar(unsigned int k) {
    __syncthreads();
    if (threadIdx.x == 0) {
        unsigned int* bar = &g_bar;
        asm volatile("red.release.gpu.global.add.u32 [%0], 1;" :: "l"(bar) : "memory");
        unsigned int target = NCTA_SOLVE * k;
        unsigned int cur;
        do {
            asm volatile("ld.acquire.gpu.global.u32 %0, [%1];" : "=r"(cur) : "l"(bar) : "memory");
            if (cur >= target) break;
            __nanosleep(64);
        } while (true);
    }
    __syncthreads();
}

__global__ void __launch_bounds__(256, 2) solve_k()
{
    extern __shared__ __align__(16) char smem[];
    const uint32_t sbase = smem_u32(smem);
    const int bx = blockIdx.x;
    const int mt = bx >> 3, nt = bx & 7;
    const int m0 = mt * 128, n0 = nt * 128;
    const int tid = threadIdx.x, lane = tid & 31, wid = tid >> 5;
    const int wm = wid >> 1, wn = wid & 1;
    const float alpha = g_alpha;

    // initX: X = alpha*C, + bf16 split into ping buffer 0
    #pragma unroll 4
    for (int e = 0; e < 64; e++) {
        int idx = tid + e * 256;
        int m = m0 + (idx >> 7), n = n0 + (idx & 127);
        if (n < NA) {
            float v = alpha * g_Cm[m * NA + n];
            g_X[m * NA + n] = v;
            __nv_bfloat16 h = __float2bfloat16(v);
            g_XH0[(size_t)m * KPAD + n] = h;
            g_XL0[(size_t)m * KPAD + n] = __float2bfloat16(v - __bfloat162float(h));
        }
    }
    gridbar(1);

    for (int t = 0; t < RICH_ITERS; t++) {
        const __nv_bfloat16* inH = (t & 1) ? g_XH1 : g_XH0;
        const __nv_bfloat16* inL = (t & 1) ? g_XL1 : g_XL0;
        __nv_bfloat16* outH = (t & 1) ? g_XH0 : g_XH1;
        __nv_bfloat16* outL = (t & 1) ? g_XL0 : g_XL1;

        float acc[2][8][4];
        #pragma unroll
        for (int i = 0; i < 2; i++)
            #pragma unroll
            for (int j = 0; j < 8; j++)
                #pragma unroll
                for (int q = 0; q < 4; q++) acc[i][j][q] = 0.f;

        gemm_mainloop<true>(inH, inL, KPAD, BD, m0, g_SH, g_SL, KPAD, NA, n0,
                            0, KPAD / 32, sbase, acc);

        #pragma unroll
        for (int mf = 0; mf < 2; mf++) {
            #pragma unroll
            for (int hh = 0; hh < 2; hh++) {
                const int m = m0 + wm * 32 + mf * 16 + (lane >> 2) + hh * 8;
                #pragma unroll
                for (int nf = 0; nf < 8; nf++) {
                    const int nb = n0 + wn * 64 + nf * 8 + (lane & 3) * 2;
                    #pragma unroll
                    for (int j = 0; j < 2; j++) {
                        const int n = nb + j;
                        if (n >= NA) continue;
                        const float tv = acc[mf][nf][hh * 2 + j];
                        const int ix = m * NA + n;
                        float xnew = g_X[ix] + alpha * (g_Cm[ix] - tv);
                        g_X[ix] = xnew;
                        __nv_bfloat16 h = __float2bfloat16(xnew);
                        outH[(size_t)m * KPAD + n] = h;
                        outL[(size_t)m * KPAD + n] =
                            __float2bfloat16(xnew - __bfloat162float(h));
                    }
                }
            }
        }
        gridbar(2 + t);
    }

    // clip scale: ||emb_i||^2 = X_i . C_i  (rows bx*16 .. bx*16+15, 2 per warp)
    #pragma unroll
    for (int s = 0; s < 2; s++) {
        const int row = bx * 16 + wid * 2 + s;
        float d = 0.f;
        for (int j = lane; j < NA; j += 32)
            d += g_X[row * NA + j] * g_Cm[row * NA + j];
        #pragma unroll
        for (int o = 16; o > 0; o >>= 1)
            d += __shfl_down_sync(0xffffffffu, d, o);
        if (lane == 0)
            g_scale[row] = fminf(rsqrtf(fmaxf(d, 1e-30f)), 1.0f);
    }
}

// ---------------- small kernels ----------------
// fused: pub fp32 -> pubH/pubL (row-major) AND pubTH/pubTL (transposed, KPAD)
__global__ void transplit_pub_k(const float* __restrict__ pub)
{
    __shared__ float t[32][33];
    const int j0 = blockIdx.x * 32;   // KP dim
    const int i0 = blockIdx.y * 32;   // NA dim
    const int tx = threadIdx.x, ty = threadIdx.y;
    for (int r = ty; r < 32; r += 8) {
        const int i = i0 + r, j = j0 + tx;
        float v = 0.f;
        if (i < NA) {
            v = pub[(size_t)i * KP + j];
            __nv_bfloat16 h = __float2bfloat16(v);
            g_pubH[(size_t)i * KP + j] = h;
            g_pubL[(size_t)i * KP + j] = __float2bfloat16(v - __bfloat162float(h));
        }
        t[r][tx] = v;
    }
    __syncthreads();
    for (int r = ty; r < 32; r += 8) {
        const int n = j0 + r;     // pubT row (KP dim)
        const int k = i0 + tx;    // col (NA dim)
        if (k < NA) {
            const float v = t[tx][r];
            __nv_bfloat16 h = __float2bfloat16(v);
            g_pubTH[(size_t)n * KPAD + k] = h;
            g_pubTL[(size_t)n * KPAD + k] = __float2bfloat16(v - __bfloat162float(h));
        }
    }
}
__global__ void split_k(const float* __restrict__ s, __nv_bfloat16* __restrict__ h,
                        __nv_bfloat16* __restrict__ l, size_t n4) {
    size_t i = (size_t)blockIdx.x * blockDim.x + threadIdx.x;
    if (i < n4) {
        float4 v = ((const float4*)s)[i];
        float vv[4] = {v.x, v.y, v.z, v.w};
        #pragma unroll
        for (int j = 0; j < 4; j++) {
            __nv_bfloat16 hh = __float2bfloat16(vv[j]);
            h[i * 4 + j] = hh;
            l[i * 4 + j] = __float2bfloat16(vv[j] - __bfloat162float(hh));
        }
    }
}
__global__ void zerobar_k() { g_bar = 0u; }

__global__ void reduceS_split_k() {
    int idx = blockIdx.x * blockDim.x + threadIdx.x;
    if (idx < NA * NA) {
        int i = idx / NA, j = idx % NA;
        if (i >= j) {
            float s = 0.f;
            #pragma unroll
            for (int zz = 0; zz < 8; zz++) s += g_Sp[zz][idx];
            g_S[i * NA + j] = s;
            g_S[j * NA + i] = s;
            __nv_bfloat16 h = __float2bfloat16(s);
            __nv_bfloat16 l = __float2bfloat16(s - __bfloat162float(h));
            g_SH[i * KPAD + j] = h; g_SL[i * KPAD + j] = l;
            g_SH[j * KPAD + i] = h; g_SL[j * KPAD + i] = l;
        }
    }
}
__global__ void reduceC_k() {
    int idx = blockIdx.x * blockDim.x + threadIdx.x;
    if (idx < BD * NA) {
        float s = 0.f;
        #pragma unroll
        for (int zz = 0; zz < 16; zz++) s += g_Cp[zz][idx];
        g_Cm[idx] = s;
    }
}
__global__ void initv_k() {
    int j = blockIdx.x * blockDim.x + threadIdx.x;
    if (j < NA) g_v[j] = g_S[j];
}
__global__ void matvec_k() {
    const int i = blockIdx.x;
    float s = 0.f;
    for (int j = threadIdx.x; j < NA; j += 256) s += g_S[i * NA + j] * g_v[j];
    __shared__ float sh[256];
    sh[threadIdx.x] = s; __syncthreads();
    for (int o = 128; o > 0; o >>= 1) {
        if (threadIdx.x < o) sh[threadIdx.x] += sh[threadIdx.x + o];
        __syncthreads();
    }
    if (threadIdx.x == 0) g_y[i] = sh[0];
}
__global__ void vnorm_k() {
    __shared__ float sh[256]; __shared__ float lam;
    float s = 0.f;
    for (int j = threadIdx.x; j < NA; j += 256) { float y = g_y[j]; s += y * y; }
    sh[threadIdx.x] = s; __syncthreads();
    for (int o = 128; o > 0; o >>= 1) {
        if (threadIdx.x < o) sh[threadIdx.x] += sh[threadIdx.x + o];
        __syncthreads();
    }
    if (threadIdx.x == 0) { lam = sqrtf(sh[0]); g_lam = lam; }
    __syncthreads();
    for (int j = threadIdx.x; j < NA; j += 256) g_v[j] = g_y[j] / lam;
}
__global__ void alpha_k() { g_alpha = 1.25f / g_lam; }

// ---------------------------------------------------------------------------
extern "C" void kernel_launch(void* const* d_in, const int* in_sizes, int n_in,
                              void* d_out, int out_size)
{
    const float* pub  = (const float*)d_in[0];
    const float* priv = (const float*)d_in[1];
    float* out = (float*)d_out;

    cudaFuncSetAttribute(gemm_tc, cudaFuncAttributeMaxDynamicSharedMemorySize, 2 * STAGE_B);
    cudaFuncSetAttribute(solve_k, cudaFuncAttributeMaxDynamicSharedMemorySize, 2 * STAGE_B);

    __nv_bfloat16 *pubH, *pubL, *pubTH, *pubTL, *privH, *privL, *XH1, *XL1;
    float *Sp, *Cp, *scal;
    cudaGetSymbolAddress((void**)&pubH, g_pubH);
    cudaGetSymbolAddress((void**)&pubL, g_pubL);
    cudaGetSymbolAddress((void**)&pubTH, g_pubTH);
    cudaGetSymbolAddress((void**)&pubTL, g_pubTL);
    cudaGetSymbolAddress((void**)&privH, g_privH);
    cudaGetSymbolAddress((void**)&privL, g_privL);
    cudaGetSymbolAddress((void**)&XH1, g_XH1);
    cudaGetSymbolAddress((void**)&XL1, g_XL1);
    cudaGetSymbolAddress((void**)&Sp, g_Sp);
    cudaGetSymbolAddress((void**)&Cp, g_Cp);
    cudaGetSymbolAddress((void**)&scal, g_scale);

    // 1) fused transpose + split of pub; 2) split priv; 3) barrier reset
    transplit_pub_k<<<dim3(KP / 32, 32), dim3(32, 8)>>>(pub);
    {
        size_t n4 = (size_t)BD * KP / 4;
        split_k<<<(unsigned)((n4 + 255) / 256), 256>>>(priv, privH, privL, n4);
    }
    zerobar_k<<<1, 1>>>();   // launch #3 -> S GEMM is the profiled #4

    // 4) S = pub*pub^T (tri blocks, split-K 8 -> 288 active CTAs)
    gemm_tc<<<dim3(8, 8, 8), 256, 2 * STAGE_B>>>(
        pubH, pubL, KP, NA, pubH, pubL, KP, NA,
        KP, 391, Sp, (long long)NA * NA, NA, 0, nullptr, 0, nullptr, 1);
    reduceS_split_k<<<(NA * NA + 255) / 256, 256>>>();

    // 5) C = priv*pub^T (split-K 16 -> 256 CTAs)
    gemm_tc<<<dim3(8, 2, 16), 256, 2 * STAGE_B>>>(
        privH, privL, KP, BD, pubH, pubL, KP, NA,
        KP, 196, Cp, (long long)BD * NA, NA, 0, nullptr, 0, nullptr, 0);
    reduceC_k<<<(BD * NA + 255) / 256, 256>>>();

    // 6) lambda_max via power iteration; alpha = 1.25/lam
    initv_k<<<4, 256>>>();
    for (int t = 0; t < POW_ITERS; t++) {
        matvec_k<<<NA, 256>>>();
        vnorm_k<<<1, 256>>>();
    }
    alpha_k<<<1, 1>>>();

    // 7) persistent solve: initX + 11 Richardson iters + clip scale (one launch)
    solve_k<<<NCTA_SOLVE, 256, 2 * STAGE_B>>>();

    // 8) out = scale*T + clamp(priv - T, +-1e-3), T = X*pub via pubT (pipelined)
    gemm_tc<<<dim3(782, 2, 1), 256, 2 * STAGE_B>>>(
        XH1, XL1, KPAD, BD, pubTH, pubTL, KPAD, KP,
        KPAD, KPAD / 32, out, 0, KP, 1, priv, KP, scal, 0);
}